// round 13
// baseline (speedup 1.0000x reference)
#include <cuda_runtime.h>

// HardLinearAttention — algebraic collapse of P@Z@M@Z^T@Q@Z.
// d=1024, n=8192, Z is (2d+1, n+1) = (2049, 8193) float32.
//
//   v[j]  = sum_{k<8192} Z[j,k] * Z[2048,k]          (j < 1024)
//   r[k]  = sum_{j<1024} v[j] * (Z[1024+j,k] - Z[j,k])
//   out   = Z;  out[2048,k] += (alpha/8192) * r[k]
//
// k1 model (LTS-cap, path-independent): L2 traffic = 32 MB rows +
// N_blocks*32KB of u re-reads. 4 rows/block @ 256 blocks => 40 MB total
// vs 64 MB at 1 row/block. That term — not MLP — is what bound k1.

#define D       1024
#define NCOLS   8192
#define S       8193          // n+1 (row stride)
#define JCHUNKS 16
#define JPER    (D / JCHUNKS) // 64
#define RPB     4             // rows per k1 block
#define K1BLK   (D / RPB)     // 256 blocks

__device__ float g_v[D];
__device__ float g_part[JCHUNKS * S];

// ---------------- kernel 1: v[j] = dot(Z[j, :], Z[2048, :]) --------------
// Block b handles rows {b, b+256, b+512, b+768}: u[k] read ONCE per block
// per column => u L2 traffic drops 4x vs 1-row blocks. The 4 accumulators
// also keep 4 independent lines in flight per iteration.
__global__ void __launch_bounds__(256) k_compute_v(const float* __restrict__ Z) {
    const int b   = blockIdx.x;                 // 0..255
    const int tid = threadIdx.x;
    const float* __restrict__ u = Z + (size_t)2048 * S;

    const float* __restrict__ r0 = Z + (size_t)(b)        * S;
    const float* __restrict__ r1 = Z + (size_t)(b +  256) * S;
    const float* __restrict__ r2 = Z + (size_t)(b +  512) * S;
    const float* __restrict__ r3 = Z + (size_t)(b +  768) * S;

    float a0 = 0.f, a1 = 0.f, a2 = 0.f, a3 = 0.f;

    #pragma unroll 4
    for (int k = tid; k < NCOLS; k += 256) {
        const float uk = u[k];
        a0 += r0[k] * uk;
        a1 += r1[k] * uk;
        a2 += r2[k] * uk;
        a3 += r3[k] * uk;
    }

    // block reduce (4 values)
    #pragma unroll
    for (int o = 16; o > 0; o >>= 1) {
        a0 += __shfl_down_sync(0xffffffffu, a0, o);
        a1 += __shfl_down_sync(0xffffffffu, a1, o);
        a2 += __shfl_down_sync(0xffffffffu, a2, o);
        a3 += __shfl_down_sync(0xffffffffu, a3, o);
    }
    __shared__ float sr[4][8];
    const int lane = tid & 31;
    const int w    = tid >> 5;
    if (lane == 0) { sr[0][w] = a0; sr[1][w] = a1; sr[2][w] = a2; sr[3][w] = a3; }
    __syncthreads();
    if (tid < 32) {
        const int r = tid >> 3;                 // 0..3
        const int i = tid & 7;                  // 0..7
        float s = sr[r][i];
        s += __shfl_down_sync(0xffffffffu, s, 4);
        s += __shfl_down_sync(0xffffffffu, s, 2);
        s += __shfl_down_sync(0xffffffffu, s, 1);
        if (i == 0) g_v[b + 256 * r] = s;
    }
}

// ---------------- kernel 2: copy rows 0..2047 + partial r accumulation ---
// Unchanged — measured ~6.9 TB/s effective, at the roofline.
__global__ void __launch_bounds__(256) k_copy_acc(const float* __restrict__ Z,
                                                  float* __restrict__ out) {
    const int jc = blockIdx.y;
    const int k  = blockIdx.x * 256 + threadIdx.x;

    __shared__ float vs[JPER];
    if (threadIdx.x < JPER) vs[threadIdx.x] = g_v[jc * JPER + threadIdx.x];
    __syncthreads();

    if (k >= S) return;

    const int j0 = jc * JPER;
    float acc = 0.f;
    #pragma unroll 8
    for (int jj = 0; jj < JPER; jj++) {
        const size_t ia = (size_t)(j0 + jj) * S + k;
        const size_t ib = (size_t)(j0 + jj + D) * S + k;
        const float a = Z[ia];
        const float b = Z[ib];
        out[ia] = a;
        out[ib] = b;
        acc += vs[jj] * (b - a);
    }
    g_part[(size_t)jc * S + k] = acc;
}

// ---------------- kernel 3: reduce partials, write final row 2048 --------
// 129 blocks; 4 groups/block each sum 4 chunks, folded through smem.
__global__ void __launch_bounds__(256) k_final(const float* __restrict__ Z,
                                               const float* __restrict__ alpha,
                                               float* __restrict__ out) {
    __shared__ float sp[4][64];
    const int g = threadIdx.x >> 6;             // chunk group 0..3
    const int c = threadIdx.x & 63;
    const int k = blockIdx.x * 64 + c;

    float sum = 0.f;
    if (k <= NCOLS) {
        #pragma unroll
        for (int q = 0; q < 4; q++)
            sum += g_part[(size_t)(4 * g + q) * S + k];
    }
    sp[g][c] = sum;
    __syncthreads();

    if (threadIdx.x < 64) {
        const int kk = blockIdx.x * 64 + threadIdx.x;
        if (kk <= NCOLS) {
            const float tot = sp[0][threadIdx.x] + sp[1][threadIdx.x]
                            + sp[2][threadIdx.x] + sp[3][threadIdx.x];
            const float scale = alpha[0] / (float)NCOLS;
            out[(size_t)2048 * S + kk] = Z[(size_t)2048 * S + kk] + scale * tot;
        }
    }
}

extern "C" void kernel_launch(void* const* d_in, const int* in_sizes, int n_in,
                              void* d_out, int out_size) {
    const float* Z     = (const float*)d_in[0];
    const float* alpha = (const float*)d_in[1];
    float* out         = (float*)d_out;

    k_compute_v<<<K1BLK, 256>>>(Z);

    dim3 g2((S + 255) / 256, JCHUNKS);
    k_copy_acc<<<g2, 256>>>(Z, out);

    k_final<<<(NCOLS + 64) / 64, 256>>>(Z, alpha, out);   // 129 blocks
}

// round 14
// speedup vs baseline: 1.1460x; 1.1460x over previous
#include <cuda_runtime.h>
#include <cstdint>

// HardLinearAttention — algebraic collapse of P@Z@M@Z^T@Q@Z.
// d=1024, n=8192, Z is (2d+1, n+1) = (2049, 8193) float32.
//
//   v[j]  = sum_{k<8192} Z[j,k] * Z[2048,k]          (j < 1024)
//   r[k]  = sum_{j<1024} v[j] * (Z[1024+j,k] - Z[j,k])
//   out   = Z;  out[2048,k] += (alpha/8192) * r[k]
//
// k1 uses 1D bulk-TMA (cp.async.bulk): DMA-engine MLP instead of per-warp
// LDG scoreboard MLP, which measured ~3 TB/s across 6 source variants.

#define D       1024
#define NCOLS   8192
#define S       8193          // n+1 (row stride)
#define JCHUNKS 16
#define JPER    (D / JCHUNKS) // 64
#define CHUNK   2048          // k1 chunk, floats
#define NCHUNK  (NCOLS / CHUNK)
#define PADF    4             // alignment slack floats per row buffer
#define ROWB    (CHUNK + PADF)
#define CHUNK_BYTES   ((ROWB) * 4)          // 8208, mult of 16
#define U_BYTES       (CHUNK * 4)           // 8192
#define TX_BYTES      (2 * CHUNK_BYTES + U_BYTES)

__device__ float g_v[D];
__device__ float g_part[JCHUNKS * S];

__device__ __forceinline__ unsigned smem_u32(const void* p) {
    return (unsigned)__cvta_generic_to_shared(p);
}
__device__ __forceinline__ void mbar_init(unsigned mbar, unsigned cnt) {
    asm volatile("mbarrier.init.shared.b64 [%0], %1;" :: "r"(mbar), "r"(cnt) : "memory");
}
__device__ __forceinline__ void mbar_expect_tx(unsigned mbar, unsigned bytes) {
    asm volatile("mbarrier.arrive.expect_tx.shared.b64 _, [%0], %1;"
                 :: "r"(mbar), "r"(bytes) : "memory");
}
__device__ __forceinline__ void mbar_wait(unsigned mbar, unsigned phase) {
    asm volatile(
        "{\n\t"
        ".reg .pred P;\n\t"
        "WAIT_%=:\n\t"
        "mbarrier.try_wait.parity.shared.b64 P, [%0], %1;\n\t"
        "@P bra DONE_%=;\n\t"
        "bra WAIT_%=;\n\t"
        "DONE_%=:\n\t"
        "}"
        :: "r"(mbar), "r"(phase) : "memory");
}
__device__ __forceinline__ void bulk_ld(unsigned dst, const void* src,
                                        unsigned bytes, unsigned mbar) {
    asm volatile(
        "cp.async.bulk.shared::cta.global.mbarrier::complete_tx::bytes [%0], [%1], %2, [%3];"
        :: "r"(dst), "l"(src), "r"(bytes), "r"(mbar) : "memory");
}

// ---------------- kernel 1: v via double-buffered bulk-TMA ---------------
// Block b handles rows {b, b+512}. Rows start at byte offset ≡ 4h (mod 16),
// h = b mod 4 (same for b+512); bulk loads start at the aligned floor and
// the compute indexes smem with +h. u row (j=2048) is exactly 16B-aligned.
__global__ void __launch_bounds__(256) k_compute_v(const float* __restrict__ Z) {
    __shared__ __align__(16) float sa[2][ROWB];
    __shared__ __align__(16) float sb[2][ROWB];
    __shared__ __align__(16) float su[2][CHUNK];
    __shared__ __align__(8)  unsigned long long mbar[2];

    const int b   = blockIdx.x;                 // 0..511
    const int tid = threadIdx.x;
    const int h   = b & 3;                      // smem read shift

    const float* __restrict__ ra = Z + (size_t)b * S - h;          // 16B aligned
    const float* __restrict__ rb = Z + (size_t)(b + 512) * S - h;  // 16B aligned
    const float* __restrict__ u  = Z + (size_t)2048 * S;           // 16B aligned

    const unsigned mb0 = smem_u32(&mbar[0]);
    if (tid == 0) { mbar_init(mb0, 1); mbar_init(mb0 + 8, 1); }
    __syncthreads();

    auto issue = [&](int c) {
        const int st = c & 1;
        const unsigned mb = mb0 + 8u * st;
        mbar_expect_tx(mb, TX_BYTES);
        const int k0 = c * CHUNK;
        bulk_ld(smem_u32(&sa[st][0]), ra + k0, CHUNK_BYTES, mb);
        bulk_ld(smem_u32(&sb[st][0]), rb + k0, CHUNK_BYTES, mb);
        bulk_ld(smem_u32(&su[st][0]), u  + k0, U_BYTES,     mb);
    };

    if (tid == 0) { issue(0); issue(1); }

    float acc0 = 0.f, acc1 = 0.f;

    for (int c = 0; c < NCHUNK; c++) {
        const int st = c & 1;
        mbar_wait(mb0 + 8u * st, (c >> 1) & 1);

        #pragma unroll
        for (int s = 0; s < CHUNK / 256; s++) {     // 8 iters
            const int i = tid + 256 * s;
            const float uk = su[st][i];
            acc0 += sa[st][i + h] * uk;
            acc1 += sb[st][i + h] * uk;
        }

        if (c + 2 < NCHUNK) {
            __syncthreads();                        // all done reading buffer st
            if (tid == 0) issue(c + 2);
        }
    }

    // block reduce (two values)
    #pragma unroll
    for (int o = 16; o > 0; o >>= 1) {
        acc0 += __shfl_down_sync(0xffffffffu, acc0, o);
        acc1 += __shfl_down_sync(0xffffffffu, acc1, o);
    }
    __shared__ float s0[8], s1[8];
    const int lane = tid & 31;
    const int w    = tid >> 5;
    if (lane == 0) { s0[w] = acc0; s1[w] = acc1; }
    __syncthreads();
    if (w == 0) {
        acc0 = (lane < 8) ? s0[lane] : 0.f;
        acc1 = (lane < 8) ? s1[lane] : 0.f;
        #pragma unroll
        for (int o = 4; o > 0; o >>= 1) {
            acc0 += __shfl_down_sync(0xffffffffu, acc0, o);
            acc1 += __shfl_down_sync(0xffffffffu, acc1, o);
        }
        if (lane == 0) { g_v[b] = acc0; g_v[b + 512] = acc1; }
    }
}

// ---------------- kernel 2: copy rows 0..2047 + partial r accumulation ---
// Unchanged — measured ~6.9 TB/s effective, at the roofline.
__global__ void __launch_bounds__(256) k_copy_acc(const float* __restrict__ Z,
                                                  float* __restrict__ out) {
    const int jc = blockIdx.y;
    const int k  = blockIdx.x * 256 + threadIdx.x;

    __shared__ float vs[JPER];
    if (threadIdx.x < JPER) vs[threadIdx.x] = g_v[jc * JPER + threadIdx.x];
    __syncthreads();

    if (k >= S) return;

    const int j0 = jc * JPER;
    float acc = 0.f;
    #pragma unroll 8
    for (int jj = 0; jj < JPER; jj++) {
        const size_t ia = (size_t)(j0 + jj) * S + k;
        const size_t ib = (size_t)(j0 + jj + D) * S + k;
        const float a = Z[ia];
        const float b = Z[ib];
        out[ia] = a;
        out[ib] = b;
        acc += vs[jj] * (b - a);
    }
    g_part[(size_t)jc * S + k] = acc;
}

// ---------------- kernel 3: reduce partials, write final row 2048 --------
__global__ void __launch_bounds__(256) k_final(const float* __restrict__ Z,
                                               const float* __restrict__ alpha,
                                               float* __restrict__ out) {
    __shared__ float sp[4][64];
    const int g = threadIdx.x >> 6;             // chunk group 0..3
    const int c = threadIdx.x & 63;
    const int k = blockIdx.x * 64 + c;

    float sum = 0.f;
    if (k <= NCOLS) {
        #pragma unroll
        for (int q = 0; q < 4; q++)
            sum += g_part[(size_t)(4 * g + q) * S + k];
    }
    sp[g][c] = sum;
    __syncthreads();

    if (threadIdx.x < 64) {
        const int kk = blockIdx.x * 64 + threadIdx.x;
        if (kk <= NCOLS) {
            const float tot = sp[0][threadIdx.x] + sp[1][threadIdx.x]
                            + sp[2][threadIdx.x] + sp[3][threadIdx.x];
            const float scale = alpha[0] / (float)NCOLS;
            out[(size_t)2048 * S + kk] = Z[(size_t)2048 * S + kk] + scale * tot;
        }
    }
}

extern "C" void kernel_launch(void* const* d_in, const int* in_sizes, int n_in,
                              void* d_out, int out_size) {
    const float* Z     = (const float*)d_in[0];
    const float* alpha = (const float*)d_in[1];
    float* out         = (float*)d_out;

    k_compute_v<<<512, 256>>>(Z);

    dim3 g2((S + 255) / 256, JCHUNKS);
    k_copy_acc<<<g2, 256>>>(Z, out);

    k_final<<<(NCOLS + 64) / 64, 256>>>(Z, alpha, out);   // 129 blocks
}